// round 3
// baseline (speedup 1.0000x reference)
#include <cuda_runtime.h>
#include <cuda_bf16.h>
#include <cstdint>

#define N_NODES 1000000
#define N_EDGES 8000000
#define EMB 64
#define NEG_SLOPE 0.01f
#define EPS_F 1e-10f
#define SCAN_NB ((N_NODES + 1023) / 1024)   // 977

// ---------------- static device scratch (no allocation allowed) --------------
__device__ float  g_h[(size_t)N_NODES * 64];     // projected h, [node][64] (ch0: 0-31, ch1: 32-63)
__device__ float  g_denom[2 * N_NODES];          // per-row softmax denominators (2 channels)
__device__ int    g_cnt[N_NODES];                // edge count per destination row
__device__ int    g_off[N_NODES + 1];            // CSR offsets (exclusive scan of cnt)
__device__ int    g_cur[N_NODES];                // write cursors (init = off)
__device__ int    g_scol[N_EDGES];               // edge src (col) sorted by destination row
__device__ float2 g_sex[N_EDGES];                // per-edge exp(logit) for both channels, sorted
__device__ int    g_bsum[1024];                  // scan block sums

// ---------------- helpers ----------------------------------------------------
__device__ __forceinline__ float leaky(float v) { return v > 0.f ? v : NEG_SLOPE * v; }

__device__ __forceinline__ int warp_incl_scan(int v) {
    #pragma unroll
    for (int s = 1; s < 32; s <<= 1) {
        int n = __shfl_up_sync(0xffffffffu, v, s);
        if ((threadIdx.x & 31) >= s) v += n;
    }
    return v;
}

// ---------------- kernel 0: zero counters / denominators ---------------------
__global__ void zero_kernel() {
    int i = blockIdx.x * blockDim.x + threadIdx.x;
    int stride = gridDim.x * blockDim.x;
    for (int j = i; j < N_NODES; j += stride) g_cnt[j] = 0;
    for (int j = i; j < 2 * N_NODES; j += stride) g_denom[j] = 0.f;
    if (i == 0) g_off[N_NODES] = N_EDGES;
}

// ---------------- kernel 1: projection  h = leaky(ego @ W + b) ---------------
// warp per node; lane j computes output cols j (ch0) and j+32 (ch1).
__global__ void project_kernel(const float* __restrict__ ego,
                               const float* __restrict__ W,
                               const float* __restrict__ b) {
    __shared__ float Ws[64 * 64];   // Ws[k*64 + j]: col j<32 -> W[0][k][j], j>=32 -> W[1][k][j-32]
    __shared__ float Bs[64];
    int t = threadIdx.x;
    for (int idx = t; idx < 64 * 64; idx += blockDim.x) {
        int k = idx >> 6, j = idx & 63;
        int c = j >> 5, jj = j & 31;
        Ws[idx] = W[c * 2048 + k * 32 + jj];
    }
    if (t < 64) {
        int c = t >> 5;
        Bs[t] = b[c * 32 + (t & 31)];
    }
    __syncthreads();

    int lane = t & 31;
    int warp = (blockIdx.x * blockDim.x + t) >> 5;
    int nwarps = (gridDim.x * blockDim.x) >> 5;
    for (int node = warp; node < N_NODES; node += nwarps) {
        const float2 e2 = *(const float2*)(ego + (size_t)node * 64 + 2 * lane);
        float a0 = 0.f, a1 = 0.f;
        #pragma unroll
        for (int k = 0; k < 64; k++) {
            float ek = __shfl_sync(0xffffffffu, (k & 1) ? e2.y : e2.x, k >> 1);
            a0 += ek * Ws[k * 64 + lane];
            a1 += ek * Ws[k * 64 + 32 + lane];
        }
        a0 = leaky(a0 + Bs[lane]);
        a1 = leaky(a1 + Bs[32 + lane]);
        g_h[(size_t)node * 64 + lane]      = a0;
        g_h[(size_t)node * 64 + 32 + lane] = a1;
    }
}

// ---------------- kernel 2: histogram of destination rows --------------------
__global__ void hist_kernel(const int* __restrict__ row) {
    int i = blockIdx.x * blockDim.x + threadIdx.x;
    int stride = gridDim.x * blockDim.x;
    for (; i < N_EDGES; i += stride) atomicAdd(&g_cnt[row[i]], 1);
}

// ---------------- kernels 3-5: exclusive scan of g_cnt -> g_off, g_cur -------
__global__ void scan1_kernel() {
    __shared__ int wsum[32];
    int t = threadIdx.x;
    int i = blockIdx.x * 1024 + t;
    int v = (i < N_NODES) ? g_cnt[i] : 0;
    int incl = warp_incl_scan(v);
    int wid = t >> 5, lid = t & 31;
    if (lid == 31) wsum[wid] = incl;
    __syncthreads();
    if (wid == 0) {
        int w = wsum[lid];
        int ws = warp_incl_scan(w);
        wsum[lid] = ws - w;    // exclusive warp prefix
    }
    __syncthreads();
    int excl = incl - v + wsum[wid];
    if (i < N_NODES) g_off[i] = excl;
    if (t == 1023) g_bsum[blockIdx.x] = excl + v;  // block total
}

__global__ void scan2_kernel() {
    __shared__ int wsum[32];
    int t = threadIdx.x;
    int v = (t < SCAN_NB) ? g_bsum[t] : 0;
    int incl = warp_incl_scan(v);
    int wid = t >> 5, lid = t & 31;
    if (lid == 31) wsum[wid] = incl;
    __syncthreads();
    if (wid == 0) {
        int w = wsum[lid];
        int ws = warp_incl_scan(w);
        wsum[lid] = ws - w;
    }
    __syncthreads();
    int excl = incl - v + wsum[wid];
    if (t < SCAN_NB) g_bsum[t] = excl;
}

__global__ void scan3_kernel() {
    int i = blockIdx.x * 1024 + threadIdx.x;
    if (i < N_NODES) {
        int off = g_off[i] + g_bsum[blockIdx.x];
        g_off[i] = off;
        g_cur[i] = off;
    }
}

// ---------------- kernel 6: edge pass ----------------------------------------
// Computes logits + exp, accumulates denominators, and counting-sorts edges
// into destination-row order. 2 edges per warp: 16-lane group per edge,
// lane s loads float4 (4 floats) -> 64 floats of h per edge operand (256B coalesced).
__global__ void edge_kernel(const int* __restrict__ row, const int* __restrict__ col) {
    int t = blockIdx.x * blockDim.x + threadIdx.x;
    int lane = t & 31;
    int g = lane >> 4;     // edge group within warp (0/1)
    int s = lane & 15;     // lane within group; s 0-7: ch0, 8-15: ch1
    long warp = t >> 5;
    long nwarps = (long)(gridDim.x * blockDim.x) >> 5;
    for (long base = warp * 2; base < N_EDGES; base += nwarps * 2) {
        long e = base + g;
        bool valid = (e < N_EDGES);
        long ee = valid ? e : 0;
        int r = row[ee];
        int c = col[ee];
        const float4 hr = *(const float4*)(g_h + (size_t)r * 64 + 4 * s);
        const float4 hc = *(const float4*)(g_h + (size_t)c * 64 + 4 * s);
        float p = hr.x * hc.x + hr.y * hc.y + hr.z * hc.z + hr.w * hc.w;
        // reduce within each 8-lane channel subgroup
        p += __shfl_xor_sync(0xffffffffu, p, 4);
        p += __shfl_xor_sync(0xffffffffu, p, 2);
        p += __shfl_xor_sync(0xffffffffu, p, 1);
        float ex = __expf(leaky(p));                         // per-channel exp(logit)
        float exo = __shfl_xor_sync(0xffffffffu, ex, 8);     // other channel's value
        if (valid && s == 0) {
            int pos = atomicAdd(&g_cur[r], 1);
            g_scol[pos] = c;
            g_sex[pos] = make_float2(ex, exo);
            atomicAdd(&g_denom[2 * r],     ex);
            atomicAdd(&g_denom[2 * r + 1], exo);
        }
    }
}

// ---------------- kernel 7: per-row aggregation ------------------------------
// 2 rows per warp (16-lane group per row). Register accumulation, single
// coalesced 256B store per row. No atomics on output.
__global__ void row_kernel(float* __restrict__ out) {
    int t = blockIdx.x * blockDim.x + threadIdx.x;
    int lane = t & 31;
    int g = lane >> 4;
    int s = lane & 15;
    int ch = s >> 3;
    long warp = t >> 5;
    long nwarps = (long)(gridDim.x * blockDim.x) >> 5;
    for (long base = warp * 2; base < N_NODES; base += nwarps * 2) {
        long rl = base + g;
        bool valid = (rl < N_NODES);
        int r = valid ? (int)rl : 0;
        int start = g_off[r];
        int end   = g_off[r + 1];
        if (!valid) { start = 0; end = 0; }
        float den = g_denom[2 * r + ch];
        float scale = 1.0f / (den + EPS_F);
        float4 acc = make_float4(0.f, 0.f, 0.f, 0.f);
        for (int i = start; i < end; i++) {
            int c = g_scol[i];
            float2 exv = g_sex[i];
            float w = (ch ? exv.y : exv.x) * scale;
            const float4 hc = *(const float4*)(g_h + (size_t)c * 64 + 4 * s);
            acc.x += w * hc.x;
            acc.y += w * hc.y;
            acc.z += w * hc.z;
            acc.w += w * hc.w;
        }
        if (valid) *(float4*)(out + (size_t)r * 64 + 4 * s) = acc;
    }
}

// ---------------- launcher ---------------------------------------------------
extern "C" void kernel_launch(void* const* d_in, const int* in_sizes, int n_in,
                              void* d_out, int out_size) {
    const float* ego = (const float*)d_in[0];   // [1M, 64] f32
    const float* W   = (const float*)d_in[1];   // [2, 64, 32] f32
    const float* b   = (const float*)d_in[2];   // [2, 1, 32] f32
    const int* row   = (const int*)d_in[3];     // [8M] i32 (destination)
    const int* col   = (const int*)d_in[4];     // [8M] i32 (source)
    float* out       = (float*)d_out;           // [1M, 64] f32

    zero_kernel<<<2048, 256>>>();
    project_kernel<<<2368, 128>>>(ego, W, b);
    hist_kernel<<<8192, 256>>>(row);
    scan1_kernel<<<SCAN_NB, 1024>>>();
    scan2_kernel<<<1, 1024>>>();
    scan3_kernel<<<SCAN_NB, 1024>>>();
    edge_kernel<<<8192, 256>>>(row, col);
    row_kernel<<<62500, 256>>>(out);
}

// round 6
// speedup vs baseline: 1.4774x; 1.4774x over previous
#include <cuda_runtime.h>
#include <cuda_bf16.h>
#include <cstdint>

#define N_NODES 1000000
#define N_EDGES 8000000
#define NEG_SLOPE 0.01f
#define EPS_F 1e-10f
#define SCAN_NB ((N_NODES + 1023) / 1024)   // 977

// ---------------- static device scratch (no allocation allowed) --------------
__device__ float g_h[(size_t)N_NODES * 64];   // projected h: [node][64], ch0 cols 0-31, ch1 cols 32-63
__device__ int   g_cnt[N_NODES];              // edge count per destination row
__device__ int   g_off[N_NODES + 1];          // CSR offsets (exclusive scan of cnt)
__device__ int   g_cur[N_NODES];              // write cursors (init = off)
__device__ int   g_scol[N_EDGES];             // edge src (col) sorted by destination row
__device__ int   g_bsum[1024];                // scan block sums

// ---------------- helpers ----------------------------------------------------
__device__ __forceinline__ float leaky(float v) { return v > 0.f ? v : NEG_SLOPE * v; }

__device__ __forceinline__ void fma_f32x2(unsigned long long& d,
                                          unsigned long long a,
                                          unsigned long long b) {
    asm("fma.rn.f32x2 %0, %1, %2, %0;" : "+l"(d) : "l"(a), "l"(b));
}
__device__ __forceinline__ unsigned long long pack2(float x, float y) {
    unsigned long long r;
    asm("mov.b64 %0, {%1, %2};" : "=l"(r) : "f"(x), "f"(y));
    return r;
}
__device__ __forceinline__ float2 unpack2(unsigned long long v) {
    float2 r;
    asm("mov.b64 {%0, %1}, %2;" : "=f"(r.x), "=f"(r.y) : "l"(v));
    return r;
}

__device__ __forceinline__ int warp_incl_scan(int v) {
    #pragma unroll
    for (int s = 1; s < 32; s <<= 1) {
        int n = __shfl_up_sync(0xffffffffu, v, s);
        if ((threadIdx.x & 31) >= s) v += n;
    }
    return v;
}

// ---------------- kernel 0: zero counters ------------------------------------
__global__ void zero_kernel() {
    int i = blockIdx.x * blockDim.x + threadIdx.x;
    int stride = gridDim.x * blockDim.x;
    for (int j = i; j < N_NODES; j += stride) g_cnt[j] = 0;
    if (i == 0) g_off[N_NODES] = N_EDGES;
}

// ---------------- kernel 1: projection  h = leaky(ego @ W + b) ---------------
// 4 nodes per warp; lane j computes (ch0 col j, ch1 col j) packed as f32x2.
// W read from shared once per (k, 4-node batch); FFMA2 halves fma-pipe load.
__global__ void project_kernel(const float* __restrict__ ego,
                               const float* __restrict__ W,
                               const float* __restrict__ b) {
    __shared__ unsigned long long Ws2[64 * 32];   // (W0[k][j], W1[k][j])
    __shared__ unsigned long long Bs2[32];
    int t = threadIdx.x;
    for (int idx = t; idx < 64 * 32; idx += blockDim.x) {
        int k = idx >> 5, j = idx & 31;
        Ws2[idx] = pack2(W[k * 32 + j], W[2048 + k * 32 + j]);
    }
    if (t < 32) Bs2[t] = pack2(b[t], b[32 + t]);
    __syncthreads();

    int lane = t & 31;
    int warp = (blockIdx.x * blockDim.x + t) >> 5;
    int nwarps = (gridDim.x * blockDim.x) >> 5;
    // N_NODES divisible by 4: uniform trip counts per warp
    for (int base = warp * 4; base < N_NODES; base += nwarps * 4) {
        float2 e0 = *(const float2*)(ego + (size_t)(base + 0) * 64 + 2 * lane);
        float2 e1 = *(const float2*)(ego + (size_t)(base + 1) * 64 + 2 * lane);
        float2 e2 = *(const float2*)(ego + (size_t)(base + 2) * 64 + 2 * lane);
        float2 e3 = *(const float2*)(ego + (size_t)(base + 3) * 64 + 2 * lane);
        unsigned long long a0 = Bs2[lane], a1 = a0, a2 = a0, a3 = a0;
        #pragma unroll
        for (int k = 0; k < 64; k++) {
            unsigned long long wv = Ws2[k * 32 + lane];
            float s0 = __shfl_sync(0xffffffffu, (k & 1) ? e0.y : e0.x, k >> 1);
            float s1 = __shfl_sync(0xffffffffu, (k & 1) ? e1.y : e1.x, k >> 1);
            float s2 = __shfl_sync(0xffffffffu, (k & 1) ? e2.y : e2.x, k >> 1);
            float s3 = __shfl_sync(0xffffffffu, (k & 1) ? e3.y : e3.x, k >> 1);
            fma_f32x2(a0, pack2(s0, s0), wv);
            fma_f32x2(a1, pack2(s1, s1), wv);
            fma_f32x2(a2, pack2(s2, s2), wv);
            fma_f32x2(a3, pack2(s3, s3), wv);
        }
        float2 r0 = unpack2(a0), r1 = unpack2(a1), r2 = unpack2(a2), r3 = unpack2(a3);
        g_h[(size_t)(base + 0) * 64 + lane]      = leaky(r0.x);
        g_h[(size_t)(base + 0) * 64 + 32 + lane] = leaky(r0.y);
        g_h[(size_t)(base + 1) * 64 + lane]      = leaky(r1.x);
        g_h[(size_t)(base + 1) * 64 + 32 + lane] = leaky(r1.y);
        g_h[(size_t)(base + 2) * 64 + lane]      = leaky(r2.x);
        g_h[(size_t)(base + 2) * 64 + 32 + lane] = leaky(r2.y);
        g_h[(size_t)(base + 3) * 64 + lane]      = leaky(r3.x);
        g_h[(size_t)(base + 3) * 64 + 32 + lane] = leaky(r3.y);
    }
}

// ---------------- kernel 2: histogram of destination rows --------------------
__global__ void hist_kernel(const int* __restrict__ row) {
    int i = blockIdx.x * blockDim.x + threadIdx.x;
    int stride = gridDim.x * blockDim.x;
    for (; i < N_EDGES; i += stride) atomicAdd(&g_cnt[row[i]], 1);
}

// ---------------- kernels 3-5: exclusive scan of g_cnt -> g_off, g_cur -------
__global__ void scan1_kernel() {
    __shared__ int wsum[32];
    int t = threadIdx.x;
    int i = blockIdx.x * 1024 + t;
    int v = (i < N_NODES) ? g_cnt[i] : 0;
    int incl = warp_incl_scan(v);
    int wid = t >> 5, lid = t & 31;
    if (lid == 31) wsum[wid] = incl;
    __syncthreads();
    if (wid == 0) {
        int w = wsum[lid];
        int ws = warp_incl_scan(w);
        wsum[lid] = ws - w;
    }
    __syncthreads();
    int excl = incl - v + wsum[wid];
    if (i < N_NODES) g_off[i] = excl;
    if (t == 1023) g_bsum[blockIdx.x] = excl + v;
}

__global__ void scan2_kernel() {
    __shared__ int wsum[32];
    int t = threadIdx.x;
    int v = (t < SCAN_NB) ? g_bsum[t] : 0;
    int incl = warp_incl_scan(v);
    int wid = t >> 5, lid = t & 31;
    if (lid == 31) wsum[wid] = incl;
    __syncthreads();
    if (wid == 0) {
        int w = wsum[lid];
        int ws = warp_incl_scan(w);
        wsum[lid] = ws - w;
    }
    __syncthreads();
    int excl = incl - v + wsum[wid];
    if (t < SCAN_NB) g_bsum[t] = excl;
}

__global__ void scan3_kernel() {
    int i = blockIdx.x * 1024 + threadIdx.x;
    if (i < N_NODES) {
        int off = g_off[i] + g_bsum[blockIdx.x];
        g_off[i] = off;
        g_cur[i] = off;
    }
}

// ---------------- kernel 6: permute (counting sort of col by destination) ----
__global__ void permute_kernel(const int* __restrict__ row, const int* __restrict__ col) {
    int i = blockIdx.x * blockDim.x + threadIdx.x;
    int stride = gridDim.x * blockDim.x;
    for (; i < N_EDGES; i += stride) {
        int r = row[i];
        int c = col[i];
        int pos = atomicAdd(&g_cur[r], 1);
        g_scol[pos] = c;
    }
}

// ---------------- kernel 7: fused logits + softmax + aggregation -------------
// 2 rows per warp, 16 lanes per row. h[row] held in registers; h[col] gathered
// ONCE per edge; sum_ex and sum(ex*h_col) accumulated together:
//   out = sum(ex*h_col) / (sum_ex + EPS)  ==  segment softmax-weighted sum.
// Depth-2 software pipeline on the h[col] gather.
__global__ void row_kernel(float* __restrict__ out) {
    int t = blockIdx.x * blockDim.x + threadIdx.x;
    int lane = t & 31;
    int g = lane >> 4;                       // row group in warp (0/1)
    int s = lane & 15;                       // lane in group: 0-7 ch0, 8-15 ch1
    unsigned gmask = g ? 0xFFFF0000u : 0x0000FFFFu;
    long warp = t >> 5;
    long nwarps = (long)(gridDim.x * blockDim.x) >> 5;
    for (long base = warp * 2; base < N_NODES; base += nwarps * 2) {
        long rl = base + g;
        bool valid = (rl < N_NODES);
        int r = valid ? (int)rl : 0;
        int start = g_off[r];
        int end   = g_off[r + 1];
        if (!valid) { start = 0; end = 0; }
        const float4 hr = *(const float4*)(g_h + (size_t)r * 64 + 4 * s);

        float sum_ex = 0.f;
        float4 acc = make_float4(0.f, 0.f, 0.f, 0.f);

        int i = start;
        int c_cur = (i < end) ? g_scol[i] : 0;
        float4 hc = (i < end) ? *(const float4*)(g_h + (size_t)c_cur * 64 + 4 * s)
                              : make_float4(0.f, 0.f, 0.f, 0.f);
        for (; i < end; i++) {
            // prefetch next gather before consuming current (MLP=2 per group)
            float4 hn = make_float4(0.f, 0.f, 0.f, 0.f);
            if (i + 1 < end) {
                int c_next = g_scol[i + 1];
                hn = *(const float4*)(g_h + (size_t)c_next * 64 + 4 * s);
            }
            float p = hr.x * hc.x + hr.y * hc.y + hr.z * hc.z + hr.w * hc.w;
            p += __shfl_xor_sync(gmask, p, 4);
            p += __shfl_xor_sync(gmask, p, 2);
            p += __shfl_xor_sync(gmask, p, 1);
            float ex = __expf(leaky(p));
            sum_ex += ex;
            acc.x += ex * hc.x;
            acc.y += ex * hc.y;
            acc.z += ex * hc.z;
            acc.w += ex * hc.w;
            hc = hn;
        }
        if (valid) {
            float scale = 1.0f / (sum_ex + EPS_F);
            float4 o = make_float4(acc.x * scale, acc.y * scale,
                                   acc.z * scale, acc.w * scale);
            *(float4*)(out + (size_t)r * 64 + 4 * s) = o;
        }
    }
}

// ---------------- launcher ---------------------------------------------------
extern "C" void kernel_launch(void* const* d_in, const int* in_sizes, int n_in,
                              void* d_out, int out_size) {
    const float* ego = (const float*)d_in[0];   // [1M, 64] f32
    const float* W   = (const float*)d_in[1];   // [2, 64, 32] f32
    const float* b   = (const float*)d_in[2];   // [2, 1, 32] f32
    const int* row   = (const int*)d_in[3];     // [8M] i32 (destination)
    const int* col   = (const int*)d_in[4];     // [8M] i32 (source)
    float* out       = (float*)d_out;           // [1M, 64] f32

    zero_kernel<<<1024, 256>>>();
    project_kernel<<<2048, 256>>>(ego, W, b);
    hist_kernel<<<8192, 256>>>(row);
    scan1_kernel<<<SCAN_NB, 1024>>>();
    scan2_kernel<<<1, 1024>>>();
    scan3_kernel<<<SCAN_NB, 1024>>>();
    permute_kernel<<<8192, 256>>>(row, col);
    row_kernel<<<62500, 256>>>(out);
}

// round 8
// speedup vs baseline: 2.0749x; 1.4044x over previous
#include <cuda_runtime.h>
#include <cuda_bf16.h>
#include <cstdint>

#define N_NODES 1000000
#define N_EDGES 8000000
#define NEG_SLOPE 0.01f
#define EPS_F 1e-10f
#define SCAN_NB ((N_NODES + 1023) / 1024)   // 977

// ---------------- static device scratch (no allocation allowed) --------------
__device__ float g_h[(size_t)N_NODES * 64];   // projected h: [node][64], ch0 cols 0-31, ch1 cols 32-63
__device__ int   g_cnt[N_NODES];              // edge count per destination row
__device__ int   g_off[N_NODES + 1];          // CSR offsets (exclusive scan of cnt)
__device__ int   g_cur[N_NODES];              // write cursors (init = off)
__device__ int   g_scol[N_EDGES];             // edge src (col) sorted by destination row
__device__ int   g_bsum[1024];                // scan block sums

// ---------------- helpers ----------------------------------------------------
__device__ __forceinline__ float leaky(float v) { return v > 0.f ? v : NEG_SLOPE * v; }

__device__ __forceinline__ void fma_f32x2(unsigned long long& d,
                                          unsigned long long a,
                                          unsigned long long b) {
    asm("fma.rn.f32x2 %0, %1, %2, %0;" : "+l"(d) : "l"(a), "l"(b));
}
__device__ __forceinline__ unsigned long long pack2(float x, float y) {
    unsigned long long r;
    asm("mov.b64 %0, {%1, %2};" : "=l"(r) : "f"(x), "f"(y));
    return r;
}
__device__ __forceinline__ float2 unpack2(unsigned long long v) {
    float2 r;
    asm("mov.b64 {%0, %1}, %2;" : "=f"(r.x), "=f"(r.y) : "l"(v));
    return r;
}

__device__ __forceinline__ int warp_incl_scan(int v) {
    #pragma unroll
    for (int s = 1; s < 32; s <<= 1) {
        int n = __shfl_up_sync(0xffffffffu, v, s);
        if ((threadIdx.x & 31) >= s) v += n;
    }
    return v;
}

// ---------------- kernel 0: zero counters ------------------------------------
__global__ void zero_kernel() {
    int i = blockIdx.x * blockDim.x + threadIdx.x;
    int stride = gridDim.x * blockDim.x;
    int4* c4 = (int4*)g_cnt;
    int4 z = make_int4(0, 0, 0, 0);
    for (int j = i; j < N_NODES / 4; j += stride) c4[j] = z;
    if (i == 0) g_off[N_NODES] = N_EDGES;
}

// ---------------- kernel 1: projection  h = leaky(ego @ W + b) ---------------
// 4 nodes per warp; lane j computes (ch0 col j, ch1 col j) packed as f32x2.
__global__ void project_kernel(const float* __restrict__ ego,
                               const float* __restrict__ W,
                               const float* __restrict__ b) {
    __shared__ unsigned long long Ws2[64 * 32];   // (W0[k][j], W1[k][j])
    __shared__ unsigned long long Bs2[32];
    int t = threadIdx.x;
    for (int idx = t; idx < 64 * 32; idx += blockDim.x) {
        int k = idx >> 5, j = idx & 31;
        Ws2[idx] = pack2(W[k * 32 + j], W[2048 + k * 32 + j]);
    }
    if (t < 32) Bs2[t] = pack2(b[t], b[32 + t]);
    __syncthreads();

    int lane = t & 31;
    int warp = (blockIdx.x * blockDim.x + t) >> 5;
    int nwarps = (gridDim.x * blockDim.x) >> 5;
    for (int base = warp * 4; base < N_NODES; base += nwarps * 4) {
        float2 e0 = *(const float2*)(ego + (size_t)(base + 0) * 64 + 2 * lane);
        float2 e1 = *(const float2*)(ego + (size_t)(base + 1) * 64 + 2 * lane);
        float2 e2 = *(const float2*)(ego + (size_t)(base + 2) * 64 + 2 * lane);
        float2 e3 = *(const float2*)(ego + (size_t)(base + 3) * 64 + 2 * lane);
        unsigned long long a0 = Bs2[lane], a1 = a0, a2 = a0, a3 = a0;
        #pragma unroll
        for (int k = 0; k < 64; k++) {
            unsigned long long wv = Ws2[k * 32 + lane];
            float s0 = __shfl_sync(0xffffffffu, (k & 1) ? e0.y : e0.x, k >> 1);
            float s1 = __shfl_sync(0xffffffffu, (k & 1) ? e1.y : e1.x, k >> 1);
            float s2 = __shfl_sync(0xffffffffu, (k & 1) ? e2.y : e2.x, k >> 1);
            float s3 = __shfl_sync(0xffffffffu, (k & 1) ? e3.y : e3.x, k >> 1);
            fma_f32x2(a0, pack2(s0, s0), wv);
            fma_f32x2(a1, pack2(s1, s1), wv);
            fma_f32x2(a2, pack2(s2, s2), wv);
            fma_f32x2(a3, pack2(s3, s3), wv);
        }
        float2 r0 = unpack2(a0), r1 = unpack2(a1), r2 = unpack2(a2), r3 = unpack2(a3);
        g_h[(size_t)(base + 0) * 64 + lane]      = leaky(r0.x);
        g_h[(size_t)(base + 0) * 64 + 32 + lane] = leaky(r0.y);
        g_h[(size_t)(base + 1) * 64 + lane]      = leaky(r1.x);
        g_h[(size_t)(base + 1) * 64 + 32 + lane] = leaky(r1.y);
        g_h[(size_t)(base + 2) * 64 + lane]      = leaky(r2.x);
        g_h[(size_t)(base + 2) * 64 + 32 + lane] = leaky(r2.y);
        g_h[(size_t)(base + 3) * 64 + lane]      = leaky(r3.x);
        g_h[(size_t)(base + 3) * 64 + 32 + lane] = leaky(r3.y);
    }
}

// ---------------- kernel 2: histogram of destination rows (int4 reads) -------
__global__ void hist_kernel(const int* __restrict__ row) {
    const int4* row4 = (const int4*)row;
    int i = blockIdx.x * blockDim.x + threadIdx.x;
    int stride = gridDim.x * blockDim.x;
    for (; i < N_EDGES / 4; i += stride) {
        int4 v = row4[i];
        atomicAdd(&g_cnt[v.x], 1);
        atomicAdd(&g_cnt[v.y], 1);
        atomicAdd(&g_cnt[v.z], 1);
        atomicAdd(&g_cnt[v.w], 1);
    }
}

// ---------------- kernels 3-5: exclusive scan of g_cnt -> g_off, g_cur -------
__global__ void scan1_kernel() {
    __shared__ int wsum[32];
    int t = threadIdx.x;
    int i = blockIdx.x * 1024 + t;
    int v = (i < N_NODES) ? g_cnt[i] : 0;
    int incl = warp_incl_scan(v);
    int wid = t >> 5, lid = t & 31;
    if (lid == 31) wsum[wid] = incl;
    __syncthreads();
    if (wid == 0) {
        int w = wsum[lid];
        int ws = warp_incl_scan(w);
        wsum[lid] = ws - w;
    }
    __syncthreads();
    int excl = incl - v + wsum[wid];
    if (i < N_NODES) g_off[i] = excl;
    if (t == 1023) g_bsum[blockIdx.x] = excl + v;
}

__global__ void scan2_kernel() {
    __shared__ int wsum[32];
    int t = threadIdx.x;
    int v = (t < SCAN_NB) ? g_bsum[t] : 0;
    int incl = warp_incl_scan(v);
    int wid = t >> 5, lid = t & 31;
    if (lid == 31) wsum[wid] = incl;
    __syncthreads();
    if (wid == 0) {
        int w = wsum[lid];
        int ws = warp_incl_scan(w);
        wsum[lid] = ws - w;
    }
    __syncthreads();
    int excl = incl - v + wsum[wid];
    if (t < SCAN_NB) g_bsum[t] = excl;
}

__global__ void scan3_kernel() {
    int i = blockIdx.x * 1024 + threadIdx.x;
    if (i < N_NODES) {
        int off = g_off[i] + g_bsum[blockIdx.x];
        g_off[i] = off;
        g_cur[i] = off;
    }
}

// ---------------- kernel 6: permute (counting sort of col, int4 reads) -------
__global__ void permute_kernel(const int* __restrict__ row, const int* __restrict__ col) {
    const int4* row4 = (const int4*)row;
    const int4* col4 = (const int4*)col;
    int i = blockIdx.x * blockDim.x + threadIdx.x;
    int stride = gridDim.x * blockDim.x;
    for (; i < N_EDGES / 4; i += stride) {
        int4 r = row4[i];
        int4 c = col4[i];
        g_scol[atomicAdd(&g_cur[r.x], 1)] = c.x;
        g_scol[atomicAdd(&g_cur[r.y], 1)] = c.y;
        g_scol[atomicAdd(&g_cur[r.z], 1)] = c.z;
        g_scol[atomicAdd(&g_cur[r.w], 1)] = c.w;
    }
}

// ---------------- kernel 7: fused logits + softmax + aggregation -------------
// ONE row per warp, FOUR edge slots of 8 lanes each. Lane s of a slot loads
// the ch0 quarter (float4 @ 4s) and ch1 quarter (float4 @ 32+4s) of h[col]
// -> full 256B coalesced gather per slot, 4 edges + 4 prefetches in flight
// per warp (2x MLP vs round-5). Per-row trip count = ceil(deg/4).
//   out = sum(ex*h_col) / (sum_ex + EPS)
__global__ void row_kernel(float* __restrict__ out) {
    int t = blockIdx.x * blockDim.x + threadIdx.x;
    int lane = t & 31;
    int slot = lane >> 3;                     // 0..3: edge slot
    int s = lane & 7;                         // lane within slot
    unsigned smask = 0xFFu << (slot * 8);     // slot's 8-lane shuffle mask
    int warp = t >> 5;                        // exactly one row per warp
    if (warp >= N_NODES) return;
    int r = warp;

    int start = g_off[r];
    int end   = g_off[r + 1];
    const float4 hr0 = *(const float4*)(g_h + (size_t)r * 64 + 4 * s);
    const float4 hr1 = *(const float4*)(g_h + (size_t)r * 64 + 32 + 4 * s);

    float se0 = 0.f, se1 = 0.f;
    float4 a0 = make_float4(0.f, 0.f, 0.f, 0.f);
    float4 a1 = make_float4(0.f, 0.f, 0.f, 0.f);

    int i = start + slot;
    if (i < end) {
        int c = g_scol[i];
        float4 hc0 = *(const float4*)(g_h + (size_t)c * 64 + 4 * s);
        float4 hc1 = *(const float4*)(g_h + (size_t)c * 64 + 32 + 4 * s);
        while (true) {
            int inext = i + 4;
            bool more = inext < end;
            float4 hn0, hn1;
            if (more) {
                int cn = g_scol[inext];
                hn0 = *(const float4*)(g_h + (size_t)cn * 64 + 4 * s);
                hn1 = *(const float4*)(g_h + (size_t)cn * 64 + 32 + 4 * s);
            }
            float d0 = hr0.x * hc0.x + hr0.y * hc0.y + hr0.z * hc0.z + hr0.w * hc0.w;
            float d1 = hr1.x * hc1.x + hr1.y * hc1.y + hr1.z * hc1.z + hr1.w * hc1.w;
            d0 += __shfl_xor_sync(smask, d0, 4);
            d1 += __shfl_xor_sync(smask, d1, 4);
            d0 += __shfl_xor_sync(smask, d0, 2);
            d1 += __shfl_xor_sync(smask, d1, 2);
            d0 += __shfl_xor_sync(smask, d0, 1);
            d1 += __shfl_xor_sync(smask, d1, 1);
            float ex0 = __expf(leaky(d0));
            float ex1 = __expf(leaky(d1));
            se0 += ex0;
            se1 += ex1;
            a0.x += ex0 * hc0.x; a0.y += ex0 * hc0.y;
            a0.z += ex0 * hc0.z; a0.w += ex0 * hc0.w;
            a1.x += ex1 * hc1.x; a1.y += ex1 * hc1.y;
            a1.z += ex1 * hc1.z; a1.w += ex1 * hc1.w;
            if (!more) break;
            hc0 = hn0; hc1 = hn1; i = inext;
        }
    }
    __syncwarp();
    // combine the 4 slot partials (xor 8, then xor 16)
    #pragma unroll
    for (int off = 8; off <= 16; off <<= 1) {
        se0 += __shfl_xor_sync(0xffffffffu, se0, off);
        se1 += __shfl_xor_sync(0xffffffffu, se1, off);
        a0.x += __shfl_xor_sync(0xffffffffu, a0.x, off);
        a0.y += __shfl_xor_sync(0xffffffffu, a0.y, off);
        a0.z += __shfl_xor_sync(0xffffffffu, a0.z, off);
        a0.w += __shfl_xor_sync(0xffffffffu, a0.w, off);
        a1.x += __shfl_xor_sync(0xffffffffu, a1.x, off);
        a1.y += __shfl_xor_sync(0xffffffffu, a1.y, off);
        a1.z += __shfl_xor_sync(0xffffffffu, a1.z, off);
        a1.w += __shfl_xor_sync(0xffffffffu, a1.w, off);
    }
    if (lane < 8) {
        float sc0 = 1.0f / (se0 + EPS_F);
        float sc1 = 1.0f / (se1 + EPS_F);
        *(float4*)(out + (size_t)r * 64 + 4 * s) =
            make_float4(a0.x * sc0, a0.y * sc0, a0.z * sc0, a0.w * sc0);
        *(float4*)(out + (size_t)r * 64 + 32 + 4 * s) =
            make_float4(a1.x * sc1, a1.y * sc1, a1.z * sc1, a1.w * sc1);
    }
}

// ---------------- launcher ---------------------------------------------------
extern "C" void kernel_launch(void* const* d_in, const int* in_sizes, int n_in,
                              void* d_out, int out_size) {
    const float* ego = (const float*)d_in[0];   // [1M, 64] f32
    const float* W   = (const float*)d_in[1];   // [2, 64, 32] f32
    const float* b   = (const float*)d_in[2];   // [2, 1, 32] f32
    const int* row   = (const int*)d_in[3];     // [8M] i32 (destination)
    const int* col   = (const int*)d_in[4];     // [8M] i32 (source)
    float* out       = (float*)d_out;           // [1M, 64] f32

    zero_kernel<<<1024, 256>>>();
    project_kernel<<<2048, 256>>>(ego, W, b);
    hist_kernel<<<4096, 256>>>(row);
    scan1_kernel<<<SCAN_NB, 1024>>>();
    scan2_kernel<<<1, 1024>>>();
    scan3_kernel<<<SCAN_NB, 1024>>>();
    permute_kernel<<<4096, 256>>>(row, col);
    row_kernel<<<125000, 256>>>(out);           // exactly 1 warp per row
}